// round 2
// baseline (speedup 1.0000x reference)
#include <cuda_runtime.h>
#include <float.h>

#define BATCH 32
#define HH 1024
#define WW 1024
#define TOPK 200
#define CAND_MAX 65536
#define CPB 256   // columns per block
#define RPB 64    // rows per band

// per-image candidate compaction buffers (static device scratch — no allocs)
__device__ int d_count[BATCH];                       // zero-init at load; topk re-zeroes
__device__ unsigned long long d_cand[BATCH][CAND_MAX];

// Row-streaming separable 7x7 max-pool NMS.
// Block: 256 threads = 256 output columns, marches down a 64-row band.
// Horizontal 7-max from a double-buffered smem row; vertical 7-max via
// register van-Herk cascade: pooled[ro] = max(m3[ro-2], h[ro], m3[ro+2]).
__global__ void __launch_bounds__(256) nms_kernel(const float* __restrict__ in) {
    const int img = blockIdx.z;
    const int cx0 = blockIdx.x * CPB;
    const int ry0 = blockIdx.y * RPB;
    const int tid = threadIdx.x;
    const int lane = tid & 31;

    __shared__ float sbuf[2][CPB + 8];   // 2 x 264 floats

    const float* base = in + (size_t)img * HH * WW;

    // rolling register state (indices relative to current row r):
    float hp0 = -FLT_MAX, hp1 = -FLT_MAX, hp2 = -FLT_MAX;          // h[r-1], h[r-2], h[r-3]
    float m30 = -FLT_MAX, m31 = -FLT_MAX, m32 = -FLT_MAX, m33 = -FLT_MAX; // m3 centered r-2..r-5
    float v0 = -FLT_MAX, v1 = -FLT_MAX, v2 = -FLT_MAX;             // v[r-1], v[r-2], v[r-3]

    int p = 0;
    #pragma unroll 2
    for (int r = ry0 - 3; r <= ry0 + RPB + 2; ++r) {
        // ---- load row r (coalesced, halo -3..+2 past 256) ----
        const bool rowOK = ((unsigned)r < HH);
        const float* rowp = base + (size_t)r * WW;
        {
            int gx = cx0 - 3 + tid;
            float v = (rowOK && (unsigned)gx < WW) ? rowp[gx] : -FLT_MAX;
            sbuf[p][tid] = v;
            if (tid < 6) {
                int gx2 = cx0 - 3 + 256 + tid;
                float w = (rowOK && (unsigned)gx2 < WW) ? rowp[gx2] : -FLT_MAX;
                sbuf[p][256 + tid] = w;
            }
        }
        __syncthreads();

        // ---- horizontal 7-max for this thread's column (center = cx0+tid) ----
        float h = sbuf[p][tid];
        h = fmaxf(h, sbuf[p][tid + 1]);
        h = fmaxf(h, sbuf[p][tid + 2]);
        float vc = sbuf[p][tid + 3];
        h = fmaxf(h, vc);
        h = fmaxf(h, sbuf[p][tid + 4]);
        h = fmaxf(h, sbuf[p][tid + 5]);
        h = fmaxf(h, sbuf[p][tid + 6]);

        // ---- vertical cascade ----
        float m3n = fmaxf(fmaxf(hp1, hp0), h);        // m3 centered r-1
        float pooled = fmaxf(fmaxf(m33, hp2), m3n);   // rows (r-3)-3 .. (r-3)+3

        // ---- emit peaks for output row ro = r-3 ----
        if (r >= ry0 + 3) {
            bool found = (v2 > 0.1f) && (pooled == v2);
            unsigned mask = __ballot_sync(0xffffffffu, found);
            if (mask) {
                int leader = __ffs(mask) - 1;
                int cnt = __popc(mask);
                int base_slot = 0;
                if (lane == leader) base_slot = atomicAdd(&d_count[img], cnt);
                base_slot = __shfl_sync(0xffffffffu, base_slot, leader);
                if (found) {
                    int rank = __popc(mask & ((1u << lane) - 1u));
                    unsigned idx = (unsigned)(r - 3) * WW + (unsigned)(cx0 + tid);
                    // key: descending value, ascending index on ties (matches lax.top_k)
                    unsigned long long key =
                        ((unsigned long long)__float_as_uint(v2) << 32) |
                        (unsigned long long)(0xFFFFFFFFu - idx);
                    int slot = base_slot + rank;
                    if (slot < CAND_MAX) d_cand[img][slot] = key;
                }
            }
        }

        // ---- rotate state ----
        m33 = m32; m32 = m31; m31 = m30; m30 = m3n;
        hp2 = hp1; hp1 = hp0; hp0 = h;
        v2 = v1; v1 = v0; v0 = vc;
        p ^= 1;
    }
}

// One block per image, 1024 threads: radix-select cutoff on value bits
// (match_any-aggregated histogram), collect survivors, bitonic sort, emit.
__global__ void __launch_bounds__(1024) topk_kernel(float* __restrict__ out) {
    const int img = blockIdx.x;
    const int tid = threadIdx.x;
    const int lane = tid & 31;

    __shared__ int sn;
    __shared__ unsigned hist[256];
    __shared__ unsigned s_above, s_digit, s_total;
    __shared__ unsigned long long buf[1024];
    __shared__ int s_cnt;

    if (tid == 0) {
        int c = d_count[img];
        d_count[img] = 0;                      // re-arm for next launch
        sn = c < CAND_MAX ? c : CAND_MAX;
    }
    __syncthreads();
    const int n = sn;
    const unsigned long long* cand = d_cand[img];

    unsigned prefix = 0, above = 0;
    int shift = 24;
    bool done = false;

    for (int lev = 0; lev < 4 && !done; lev++) {
        shift = 24 - lev * 8;
        for (int i = tid; i < 256; i += 1024) hist[i] = 0;
        __syncthreads();
        for (int ib = 0; ib < n; ib += 1024) {
            int i = ib + tid;
            unsigned vb = 0;
            bool valid = false;
            if (i < n) {
                vb = (unsigned)(cand[i] >> 32);
                valid = (lev == 0) || ((vb >> (shift + 8)) == prefix);
            }
            unsigned act = __ballot_sync(0xffffffffu, valid);
            if (valid) {
                unsigned d = (vb >> shift) & 0xFFu;
                unsigned peers = __match_any_sync(act, d);
                if (lane == (__ffs(peers) - 1))
                    atomicAdd(&hist[d], (unsigned)__popc(peers));
            }
        }
        __syncthreads();
        if (tid == 0) {
            unsigned cum = 0;
            int dsel = 0;
            for (int b = 255; b >= 0; b--) {
                if (above + cum + hist[b] >= TOPK || b == 0) { dsel = b; break; }
                cum += hist[b];
            }
            s_above = above + cum;
            s_digit = (unsigned)dsel;
            s_total = above + cum + hist[dsel];
        }
        __syncthreads();
        above = s_above;
        prefix = (prefix << 8) | s_digit;
        done = (s_total <= 1024);
        __syncthreads();
    }

    // collect all candidates with value-bits >> shift >= prefix
    if (tid == 0) s_cnt = 0;
    __syncthreads();
    for (int ib = 0; ib < n; ib += 1024) {
        int i = ib + tid;
        if (i < n) {
            unsigned long long k = cand[i];
            unsigned vb = (unsigned)(k >> 32);
            if ((vb >> shift) >= prefix) {
                int pos = atomicAdd(&s_cnt, 1);
                if (pos < 1024) buf[pos] = k;
            }
        }
    }
    __syncthreads();
    int m = s_cnt < 1024 ? s_cnt : 1024;
    if (tid >= m) buf[tid] = 0ull;
    __syncthreads();

    // bitonic sort 1024 keys, descending
    for (int k = 2; k <= 1024; k <<= 1) {
        for (int j = k >> 1; j > 0; j >>= 1) {
            int ixj = tid ^ j;
            if (ixj > tid) {
                unsigned long long a = buf[tid], b = buf[ixj];
                bool swap = ((tid & k) == 0) ? (a < b) : (a > b);
                if (swap) { buf[tid] = b; buf[ixj] = a; }
            }
            __syncthreads();
        }
    }

    // emit: coords [B, K, 2] (row, col) then probs [B, K], all fp32
    float* coords = out;
    float* probs = out + (size_t)BATCH * TOPK * 2;
    if (tid < TOPK) {
        unsigned long long key = buf[tid];
        float prob;
        unsigned row, col;
        if (key == 0ull) {
            prob = 0.0f; row = 0; col = 0;
        } else {
            prob = __uint_as_float((unsigned)(key >> 32));
            unsigned idx = 0xFFFFFFFFu - (unsigned)(key & 0xFFFFFFFFull);
            row = idx / WW;
            col = idx % WW;
        }
        size_t o = (size_t)img * TOPK + tid;
        coords[o * 2 + 0] = (float)row;
        coords[o * 2 + 1] = (float)col;
        probs[o] = prob;
    }
}

extern "C" void kernel_launch(void* const* d_in, const int* in_sizes, int n_in,
                              void* d_out, int out_size) {
    const float* in = (const float*)d_in[0];
    float* out = (float*)d_out;

    dim3 grid(WW / CPB, HH / RPB, BATCH);   // 4 x 16 x 32 = 2048 blocks
    nms_kernel<<<grid, CPB>>>(in);
    topk_kernel<<<BATCH, 1024>>>(out);
}

// round 3
// speedup vs baseline: 1.0382x; 1.0382x over previous
#include <cuda_runtime.h>
#include <float.h>

#define BATCH 32
#define HH 1024
#define WW 1024
#define TOPK 200
#define CAND_MAX 65536
#define HOTCAP 16384
#define COLDCAP (CAND_MAX - HOTCAP)
#define HOT_T 0.9993f
#define OUTC 26      // output columns per warp
#define NWX 40       // warp strips across width (40*26 = 1040 >= 1024)
#define WPB 8        // warps per block
#define RPB 128      // rows per block band

// static device scratch (no allocs). d_cnt packs hot<<32 | cold, re-armed by topk.
__device__ unsigned long long d_cnt[BATCH];
__device__ unsigned long long d_cand[BATCH][CAND_MAX];

// Barrier-free shuffle-based 7x7 max-pool NMS.
// Warp owns a 26-col output strip; marches down a 128-row band, 4 rows/iter.
__global__ void __launch_bounds__(256) nms_kernel(const float* __restrict__ in,
                                                  int img_base) {
    const int img = img_base + blockIdx.z;
    const int wid = threadIdx.x >> 5;
    const int lane = threadIdx.x & 31;
    const int gwx = blockIdx.x * WPB + wid;          // 0..39
    const int out0 = gwx * OUTC;
    const int col = out0 - 3 + lane;                 // loaded column
    const bool colOK = ((unsigned)col < WW);
    const bool outlane = (lane < OUTC) && (out0 + lane < WW);
    const int ry0 = blockIdx.y * RPB;
    const int rend = ry0 + RPB + 2;                  // last row fed in (inclusive)
    const float* base = in + (size_t)img * HH * WW;

    // rolling vertical state: h[r-1..r-3], m3 centered r-2..r-5, center v[r-1..r-3]
    float hp0 = -FLT_MAX, hp1 = -FLT_MAX, hp2 = -FLT_MAX;
    float m30 = -FLT_MAX, m31 = -FLT_MAX, m32 = -FLT_MAX, m33 = -FLT_MAX;
    float cv0 = -FLT_MAX, cv1 = -FLT_MAX, cv2 = -FLT_MAX;

    for (int rb = ry0 - 3; rb <= rend; rb += 4) {
        // batched loads: MLP = 4
        float v[4];
        #pragma unroll
        for (int k = 0; k < 4; k++) {
            int r = rb + k;
            v[k] = (colOK && (unsigned)r < HH && r <= rend)
                       ? base[(size_t)r * WW + col] : -FLT_MAX;
        }
        #pragma unroll
        for (int k = 0; k < 4; k++) {
            int r = rb + k;
            if (r <= rend) {
                // horizontal 7-max via log-step shuffles: c(l) = max cols [l, l+6]
                float a = fmaxf(v[k], __shfl_down_sync(0xffffffffu, v[k], 1));
                float b = fmaxf(a, __shfl_down_sync(0xffffffffu, a, 2));
                float h = fmaxf(b, __shfl_down_sync(0xffffffffu, b, 3));
                float cv = __shfl_down_sync(0xffffffffu, v[k], 3); // center col value
                // vertical cascade
                float m3n = fmaxf(fmaxf(hp1, hp0), h);
                float pooled = fmaxf(fmaxf(m33, hp2), m3n);        // 7-row window @ r-3

                if (r >= ry0 + 3) {
                    bool peak = outlane && (cv2 > 0.1f) && (pooled == cv2);
                    bool hot = peak && (cv2 > HOT_T);
                    unsigned mp = __ballot_sync(0xffffffffu, peak);
                    unsigned mh = __ballot_sync(0xffffffffu, hot);
                    if (mp) {
                        int leader = __ffs(mp) - 1;
                        unsigned nh = (unsigned)__popc(mh);
                        unsigned nc = (unsigned)__popc(mp & ~mh);
                        unsigned long long bases = 0;
                        if (lane == leader)
                            bases = atomicAdd(&d_cnt[img],
                                              ((unsigned long long)nh << 32) | nc);
                        bases = __shfl_sync(0xffffffffu, bases, leader);
                        if (peak) {
                            unsigned idx = (unsigned)(r - 3) * WW + (unsigned)(out0 + lane);
                            // key: descending value, ascending index on ties
                            unsigned long long key =
                                ((unsigned long long)__float_as_uint(cv2) << 32) |
                                (unsigned long long)(0xFFFFFFFFu - idx);
                            unsigned lanemask = (1u << lane) - 1u;
                            if (hot) {
                                unsigned slot = (unsigned)(bases >> 32) + __popc(mh & lanemask);
                                if (slot < HOTCAP) d_cand[img][slot] = key;
                            } else {
                                unsigned slot = (unsigned)bases + __popc((mp & ~mh) & lanemask);
                                if (slot < COLDCAP) d_cand[img][CAND_MAX - 1 - slot] = key;
                            }
                        }
                    }
                }
                // rotate state
                m33 = m32; m32 = m31; m31 = m30; m30 = m3n;
                hp2 = hp1; hp1 = hp0; hp0 = h;
                cv2 = cv1; cv1 = cv0; cv0 = cv;
            }
        }
    }
}

// One block per image. Fast path: hot list (values > HOT_T) fits [TOPK, 1024]
// -> direct bitonic sort. Fallback: radix-select over hot+cold, then sort.
__global__ void __launch_bounds__(1024) topk_kernel(float* __restrict__ out) {
    const int img = blockIdx.x;
    const int tid = threadIdx.x;
    const int lane = tid & 31;

    __shared__ int s_nh, s_nc;
    __shared__ unsigned long long buf[1024];
    __shared__ unsigned hist[256];
    __shared__ unsigned s_above, s_digit, s_total;
    __shared__ int s_cnt;

    if (tid == 0) {
        unsigned long long c = d_cnt[img];
        d_cnt[img] = 0;                               // re-arm for next replay
        int nh = (int)(c >> 32), nc = (int)(c & 0xFFFFFFFFull);
        s_nh = nh < HOTCAP ? nh : HOTCAP;
        s_nc = nc < COLDCAP ? nc : COLDCAP;
    }
    __syncthreads();
    const int nh = s_nh, nc = s_nc;
    const unsigned long long* cand = d_cand[img];

    if (nh >= TOPK && nh <= 1024) {
        // ---- fast path: hot list contains the full top-K ----
        buf[tid] = (tid < nh) ? cand[tid] : 0ull;
    } else {
        // ---- fallback: radix-select over combined hot+cold (rarely taken) ----
        const int n = nh + nc;
        unsigned prefix = 0, above = 0;
        int shift = 24;
        bool done = false;
        for (int lev = 0; lev < 4 && !done; lev++) {
            shift = 24 - lev * 8;
            for (int i = tid; i < 256; i += 1024) hist[i] = 0;
            __syncthreads();
            for (int ib = 0; ib < n; ib += 1024) {
                int i = ib + tid;
                unsigned vb = 0; bool valid = false;
                if (i < n) {
                    int j = (i < nh) ? i : (CAND_MAX - nc + (i - nh));
                    vb = (unsigned)(cand[j] >> 32);
                    valid = (lev == 0) || ((vb >> (shift + 8)) == prefix);
                }
                unsigned act = __ballot_sync(0xffffffffu, valid);
                if (valid) {
                    unsigned d = (vb >> shift) & 0xFFu;
                    unsigned peers = __match_any_sync(act, d);
                    if (lane == (__ffs(peers) - 1))
                        atomicAdd(&hist[d], (unsigned)__popc(peers));
                }
            }
            __syncthreads();
            if (tid == 0) {
                unsigned cum = 0; int dsel = 0;
                for (int b = 255; b >= 0; b--) {
                    if (above + cum + hist[b] >= TOPK || b == 0) { dsel = b; break; }
                    cum += hist[b];
                }
                s_above = above + cum;
                s_digit = (unsigned)dsel;
                s_total = above + cum + hist[dsel];
            }
            __syncthreads();
            above = s_above;
            prefix = (prefix << 8) | s_digit;
            done = (s_total <= 1024);
            __syncthreads();
        }
        if (tid == 0) s_cnt = 0;
        __syncthreads();
        for (int ib = 0; ib < n; ib += 1024) {
            int i = ib + tid;
            if (i < n) {
                int j = (i < nh) ? i : (CAND_MAX - nc + (i - nh));
                unsigned long long k = cand[j];
                if (((unsigned)(k >> 32) >> shift) >= prefix) {
                    int pos = atomicAdd(&s_cnt, 1);
                    if (pos < 1024) buf[pos] = k;
                }
            }
        }
        __syncthreads();
        int m = s_cnt < 1024 ? s_cnt : 1024;
        if (tid >= m) buf[tid] = 0ull;
    }
    __syncthreads();

    // bitonic sort 1024 keys, descending
    for (int k = 2; k <= 1024; k <<= 1) {
        for (int j = k >> 1; j > 0; j >>= 1) {
            int ixj = tid ^ j;
            if (ixj > tid) {
                unsigned long long a = buf[tid], b = buf[ixj];
                bool sw = ((tid & k) == 0) ? (a < b) : (a > b);
                if (sw) { buf[tid] = b; buf[ixj] = a; }
            }
            __syncthreads();
        }
    }

    // emit: coords [B, K, 2] (row, col) then probs [B, K], all fp32
    float* coords = out;
    float* probs = out + (size_t)BATCH * TOPK * 2;
    if (tid < TOPK) {
        unsigned long long key = buf[tid];
        float prob; unsigned row, col;
        if (key == 0ull) {
            prob = 0.0f; row = 0; col = 0;
        } else {
            prob = __uint_as_float((unsigned)(key >> 32));
            unsigned idx = 0xFFFFFFFFu - (unsigned)(key & 0xFFFFFFFFull);
            row = idx / WW; col = idx % WW;
        }
        size_t o = (size_t)img * TOPK + tid;
        coords[o * 2 + 0] = (float)row;
        coords[o * 2 + 1] = (float)col;
        probs[o] = prob;
    }
}

extern "C" void kernel_launch(void* const* d_in, const int* in_sizes, int n_in,
                              void* d_out, int out_size) {
    const float* in = (const float*)d_in[0];
    float* out = (float*)d_out;

    // 3-way image split (4 launches/replay) so ncu -s5 -c1 lands on an nms launch
    dim3 g1(NWX / WPB, HH / RPB, 11);
    dim3 g2(NWX / WPB, HH / RPB, 11);
    dim3 g3(NWX / WPB, HH / RPB, 10);
    nms_kernel<<<g1, 256>>>(in, 0);
    nms_kernel<<<g2, 256>>>(in, 11);
    nms_kernel<<<g3, 256>>>(in, 22);
    topk_kernel<<<BATCH, 1024>>>(out);
}

// round 4
// speedup vs baseline: 3.1960x; 3.0783x over previous
#include <cuda_runtime.h>
#include <float.h>

#define BATCH 32
#define HH 1024
#define WW 1024
#define TOPK 200
#define HOT_T 0.9993f
#define OUTC 26          // output columns per warp strip
#define NSTRIP 40        // 40*26 = 1040 >= 1024
#define WPB 8            // warps per block
#define RPB 256          // rows per band
#define NBAND (HH / RPB) // 4
#define SEGS_PER_IMG (NSTRIP * NBAND)   // 160
#define SEGCAP 320       // slots per segment (expected ~136 peaks, hard max 448)

// static device scratch — per-warp private segments, NO atomics anywhere in nms
__device__ unsigned long long d_seg[BATCH * SEGS_PER_IMG * SEGCAP];  // ~13 MB
__device__ int d_segcnt[BATCH * SEGS_PER_IMG];

// Barrier-free, atomic-free 7x7 max-pool NMS.
// Warp owns a 26-col x 256-row tile and a private output segment.
__global__ void __launch_bounds__(256) nms_kernel(const float* __restrict__ in) {
    const int img = blockIdx.z;
    const int wid = threadIdx.x >> 5;
    const int lane = threadIdx.x & 31;
    const int strip = blockIdx.x * WPB + wid;        // 0..39
    const int band = blockIdx.y;                     // 0..3
    const int out0 = strip * OUTC;
    const int col = out0 - 3 + lane;
    const bool colOK = ((unsigned)col < WW);
    const bool outlane = (lane < OUTC) && (out0 + lane < WW);
    const int ry0 = band * RPB;
    const int rend = ry0 + RPB + 2;
    const float* base = in + (size_t)img * HH * WW;

    const int segid = (img * NBAND + band) * NSTRIP + strip;
    unsigned long long* seg = d_seg + (size_t)segid * SEGCAP;
    int wcnt = 0;

    // rolling vertical state: h[r-1..r-3], m3 centered r-2..r-5, center v[r-1..r-3]
    float hp0 = -FLT_MAX, hp1 = -FLT_MAX, hp2 = -FLT_MAX;
    float m30 = -FLT_MAX, m31 = -FLT_MAX, m32 = -FLT_MAX, m33 = -FLT_MAX;
    float cv0 = -FLT_MAX, cv1 = -FLT_MAX, cv2 = -FLT_MAX;

    for (int rb = ry0 - 3; rb <= rend; rb += 4) {
        float v[4];
        #pragma unroll
        for (int k = 0; k < 4; k++) {
            int r = rb + k;
            v[k] = (colOK && (unsigned)r < HH && r <= rend)
                       ? base[(size_t)r * WW + col] : -FLT_MAX;
        }
        #pragma unroll
        for (int k = 0; k < 4; k++) {
            int r = rb + k;
            if (r <= rend) {
                // horizontal 7-max via log-step shuffles: h(l) = max cols [l, l+6]
                float a = fmaxf(v[k], __shfl_down_sync(0xffffffffu, v[k], 1));
                float b = fmaxf(a, __shfl_down_sync(0xffffffffu, a, 2));
                float h = fmaxf(b, __shfl_down_sync(0xffffffffu, b, 3));
                float cv = __shfl_down_sync(0xffffffffu, v[k], 3);   // center col
                float m3n = fmaxf(fmaxf(hp1, hp0), h);
                float pooled = fmaxf(fmaxf(m33, hp2), m3n);          // 7 rows @ r-3

                if (r >= ry0 + 3) {
                    bool peak = outlane && (cv2 > 0.1f) && (pooled == cv2);
                    unsigned mp = __ballot_sync(0xffffffffu, peak);
                    if (mp) {
                        if (peak) {
                            int rank = __popc(mp & ((1u << lane) - 1u));
                            int slot = wcnt + rank;
                            unsigned idx = (unsigned)(r - 3) * WW
                                         + (unsigned)(out0 + lane);
                            // key: descending value, ascending index on ties
                            unsigned long long key =
                                ((unsigned long long)__float_as_uint(cv2) << 32) |
                                (unsigned long long)(0xFFFFFFFFu - idx);
                            if (slot < SEGCAP) seg[slot] = key;
                        }
                        wcnt += __popc(mp);
                    }
                }
                m33 = m32; m32 = m31; m31 = m30; m30 = m3n;
                hp2 = hp1; hp1 = hp0; hp0 = h;
                cv2 = cv1; cv1 = cv0; cv0 = cv;
            }
        }
    }
    if (lane == 0) d_segcnt[segid] = wcnt < SEGCAP ? wcnt : SEGCAP;
}

// One block per image. Pass 1 gathers "hot" keys (value > HOT_T) from segments
// into shared buf. If 200 <= hot <= 1024: sort directly. Else radix fallback.
__global__ void __launch_bounds__(1024) topk_kernel(float* __restrict__ out) {
    const int img = blockIdx.x;
    const int tid = threadIdx.x;
    const int lane = tid & 31;
    const int wrp = tid >> 5;

    __shared__ unsigned long long buf[1024];
    __shared__ int s_cnt;
    __shared__ unsigned short scnt[SEGS_PER_IMG];
    __shared__ unsigned hist[256];
    __shared__ unsigned s_above, s_digit, s_total;

    const int cbase = img * SEGS_PER_IMG;
    for (int i = tid; i < SEGS_PER_IMG; i += 1024)
        scnt[i] = (unsigned short)d_segcnt[cbase + i];
    if (tid == 0) s_cnt = 0;
    __syncthreads();

    const unsigned hotbits = __float_as_uint(HOT_T);

    // pass 1: gather hot keys (warp w handles segments w, w+32, ...)
    for (int s = wrp; s < SEGS_PER_IMG; s += 32) {
        int cnt = scnt[s];
        const unsigned long long* seg = d_seg + (size_t)(cbase + s) * SEGCAP;
        for (int i = lane; i < cnt; i += 32) {
            unsigned long long k = seg[i];
            if ((unsigned)(k >> 32) > hotbits) {
                int pos = atomicAdd(&s_cnt, 1);
                if (pos < 1024) buf[pos] = k;
            }
        }
    }
    __syncthreads();
    int nhot = s_cnt;

    if (nhot >= TOPK && nhot <= 1024) {
        if (tid >= nhot) buf[tid] = 0ull;
    } else {
        // ---- fallback: radix-select over all segment entries (off-distribution) ----
        const int NFLAT = SEGS_PER_IMG * SEGCAP;
        unsigned prefix = 0, above = 0;
        int shift = 24;
        bool done = false;
        for (int lev = 0; lev < 4 && !done; lev++) {
            shift = 24 - lev * 8;
            for (int i = tid; i < 256; i += 1024) hist[i] = 0;
            __syncthreads();
            for (int i = tid; i < NFLAT; i += 1024) {
                int s = i / SEGCAP, slot = i - s * SEGCAP;
                if (slot < scnt[s]) {
                    unsigned vb = (unsigned)(d_seg[(size_t)(cbase + s) * SEGCAP + slot] >> 32);
                    if (lev == 0 || (vb >> (shift + 8)) == prefix)
                        atomicAdd(&hist[(vb >> shift) & 0xFFu], 1u);
                }
            }
            __syncthreads();
            if (tid == 0) {
                unsigned cum = 0; int dsel = 0;
                for (int b = 255; b >= 0; b--) {
                    if (above + cum + hist[b] >= TOPK || b == 0) { dsel = b; break; }
                    cum += hist[b];
                }
                s_above = above + cum;
                s_digit = (unsigned)dsel;
                s_total = above + cum + hist[dsel];
            }
            __syncthreads();
            above = s_above;
            prefix = (prefix << 8) | s_digit;
            done = (s_total <= 1024);
            __syncthreads();
        }
        if (tid == 0) s_cnt = 0;
        __syncthreads();
        for (int i = tid; i < NFLAT; i += 1024) {
            int s = i / SEGCAP, slot = i - s * SEGCAP;
            if (slot < scnt[s]) {
                unsigned long long k = d_seg[(size_t)(cbase + s) * SEGCAP + slot];
                if (((unsigned)(k >> 32) >> shift) >= prefix) {
                    int pos = atomicAdd(&s_cnt, 1);
                    if (pos < 1024) buf[pos] = k;
                }
            }
        }
        __syncthreads();
        int m = s_cnt < 1024 ? s_cnt : 1024;
        if (tid >= m) buf[tid] = 0ull;
    }
    __syncthreads();

    // bitonic sort 1024 keys, descending
    for (int k = 2; k <= 1024; k <<= 1) {
        for (int j = k >> 1; j > 0; j >>= 1) {
            int ixj = tid ^ j;
            if (ixj > tid) {
                unsigned long long a = buf[tid], b = buf[ixj];
                bool sw = ((tid & k) == 0) ? (a < b) : (a > b);
                if (sw) { buf[tid] = b; buf[ixj] = a; }
            }
            __syncthreads();
        }
    }

    // emit: coords [B, K, 2] (row, col) then probs [B, K], all fp32
    float* coords = out;
    float* probs = out + (size_t)BATCH * TOPK * 2;
    if (tid < TOPK) {
        unsigned long long key = buf[tid];
        float prob; unsigned row, col;
        if (key == 0ull) {
            prob = 0.0f; row = 0; col = 0;
        } else {
            prob = __uint_as_float((unsigned)(key >> 32));
            unsigned idx = 0xFFFFFFFFu - (unsigned)(key & 0xFFFFFFFFull);
            row = idx / WW; col = idx % WW;
        }
        size_t o = (size_t)img * TOPK + tid;
        coords[o * 2 + 0] = (float)row;
        coords[o * 2 + 1] = (float)col;
        probs[o] = prob;
    }
}

extern "C" void kernel_launch(void* const* d_in, const int* in_sizes, int n_in,
                              void* d_out, int out_size) {
    const float* in = (const float*)d_in[0];
    float* out = (float*)d_out;

    dim3 grid(NSTRIP / WPB, NBAND, BATCH);   // 5 x 4 x 32 = 640 blocks
    nms_kernel<<<grid, 256>>>(in);
    topk_kernel<<<BATCH, 1024>>>(out);
}

// round 5
// speedup vs baseline: 4.3358x; 1.3566x over previous
#include <cuda_runtime.h>
#include <float.h>

#define BATCH 32
#define HH 1024
#define WW 1024
#define TOPK 200
#define HOT_T 0.9993f
#define STRIPS 8          // 8 strips x 128 cols
#define CPW 128           // columns per warp
#define WPB 4             // warps per block
#define RPB 32            // rows per band
#define NBAND (HH / RPB)  // 32
#define SEGS_PER_IMG (STRIPS * NBAND)   // 256
#define SEGCAP 512

// static device scratch — per-warp private segments (hot from front, cold from back)
__device__ unsigned long long d_seg[BATCH * SEGS_PER_IMG * SEGCAP];  // 32 MB
__device__ unsigned int d_segcnt[BATCH * SEGS_PER_IMG];              // hot | cold<<16

__device__ __forceinline__ float4 mk4(float x) { return make_float4(x, x, x, x); }

// Barrier-free, atomic-free, float4-vectorized 7x7 max-pool NMS.
// Warp owns a 128-col x 32-row tile; lane owns 4 columns.
__global__ void __launch_bounds__(128) nms_kernel(const float* __restrict__ in) {
    const int img = blockIdx.z;
    const int wid = threadIdx.x >> 5;
    const int lane = threadIdx.x & 31;
    const int strip = blockIdx.x * WPB + wid;       // 0..7
    const int band = blockIdx.y;                    // 0..31
    const int out0 = strip * CPW;
    const int colbase = out0 + 4 * lane;
    const int ry0 = band * RPB;
    const int rend = ry0 + RPB + 2;
    const float* base = in + (size_t)img * HH * WW;

    const int segid = (img * NBAND + band) * STRIPS + strip;
    unsigned long long* seg = d_seg + (size_t)segid * SEGCAP;
    int nhot = 0, ncold = 0;

    // halo quad: lane 0 loads left [out0-4..out0-1], lane 31 right [out0+128..+131]
    const bool haloLane = (lane == 0) || (lane == 31);
    const int hcol = (lane == 0) ? (out0 - 4) : (out0 + CPW);
    const bool haloOK = haloLane && ((unsigned)hcol < WW);

    // rolling vertical state (float4 = 4 columns): h[r-1..r-3], m3 centered
    // r-2..r-5, center v[r-1..r-3]
    float4 hp0 = mk4(-FLT_MAX), hp1 = hp0, hp2 = hp0;
    float4 m30 = hp0, m31 = hp0, m32 = hp0, m33 = hp0;
    float4 cv0 = hp0, cv1 = hp0, cv2 = hp0;

    for (int rb = ry0 - 3; rb <= rend; rb += 2) {
        float4 v[2], q[2];
        #pragma unroll
        for (int k = 0; k < 2; k++) {
            int r = rb + k;
            bool rOK = ((unsigned)r < HH) && (r <= rend);
            v[k] = mk4(-FLT_MAX);
            q[k] = mk4(-FLT_MAX);
            if (rOK)
                v[k] = *reinterpret_cast<const float4*>(base + (size_t)r * WW + colbase);
            if (rOK && haloOK)
                q[k] = *reinterpret_cast<const float4*>(base + (size_t)r * WW + hcol);
        }
        #pragma unroll
        for (int k = 0; k < 2; k++) {
            int r = rb + k;
            float4 vv = v[k], qq = q[k];
            // own-quad prefix/suffix maxes
            float p1 = fmaxf(vv.x, vv.y);
            float p2 = fmaxf(p1, vv.z);
            float p3 = fmaxf(p2, vv.w);
            float s2 = fmaxf(vv.z, vv.w);
            float s1 = fmaxf(vv.y, s2);
            // halo-quad values (only meaningful on lanes 0 / 31)
            float qs2 = fmaxf(qq.z, qq.w);
            float qs1 = fmaxf(qq.y, qs2);
            float qp1 = fmaxf(qq.x, qq.y);
            float qp2 = fmaxf(qp1, qq.z);

            float ls1 = __shfl_up_sync(0xffffffffu, s1, 1);
            float ls2 = __shfl_up_sync(0xffffffffu, s2, 1);
            float ls3 = __shfl_up_sync(0xffffffffu, vv.w, 1);
            float rp0 = __shfl_down_sync(0xffffffffu, vv.x, 1);
            float rp1 = __shfl_down_sync(0xffffffffu, p1, 1);
            float rp2 = __shfl_down_sync(0xffffffffu, p2, 1);
            if (lane == 0)  { ls1 = qs1;  ls2 = qs2;  ls3 = qq.w; }
            if (lane == 31) { rp0 = qq.x; rp1 = qp1;  rp2 = qp2;  }

            // horizontal 7-max per owned column
            float4 h;
            h.x = fmaxf(ls1, p3);
            h.y = fmaxf(fmaxf(ls2, rp0), p3);
            h.z = fmaxf(fmaxf(ls3, rp1), p3);
            h.w = fmaxf(rp2, p3);

            // vertical cascade
            float4 m3n, pooled;
            m3n.x = fmaxf(fmaxf(hp1.x, hp0.x), h.x);
            m3n.y = fmaxf(fmaxf(hp1.y, hp0.y), h.y);
            m3n.z = fmaxf(fmaxf(hp1.z, hp0.z), h.z);
            m3n.w = fmaxf(fmaxf(hp1.w, hp0.w), h.w);
            pooled.x = fmaxf(fmaxf(m33.x, hp2.x), m3n.x);
            pooled.y = fmaxf(fmaxf(m33.y, hp2.y), m3n.y);
            pooled.z = fmaxf(fmaxf(m33.z, hp2.z), m3n.z);
            pooled.w = fmaxf(fmaxf(m33.w, hp2.w), m3n.w);

            if (r >= ry0 + 3 && r <= rend) {
                float cvv[4] = {cv2.x, cv2.y, cv2.z, cv2.w};
                float pl[4]  = {pooled.x, pooled.y, pooled.z, pooled.w};
                bool pk[4];
                #pragma unroll
                for (int c = 0; c < 4; c++)
                    pk[c] = (cvv[c] > 0.1f) && (pl[c] == cvv[c]);
                unsigned any = __ballot_sync(0xffffffffu, pk[0] | pk[1] | pk[2] | pk[3]);
                if (any) {
                    unsigned below = (1u << lane) - 1u;
                    #pragma unroll
                    for (int c = 0; c < 4; c++) {
                        bool hot = pk[c] && (cvv[c] > HOT_T);
                        bool cold = pk[c] && !hot;
                        unsigned mh = __ballot_sync(0xffffffffu, hot);
                        unsigned mc = __ballot_sync(0xffffffffu, cold);
                        if (pk[c]) {
                            unsigned idx = (unsigned)(r - 3) * WW + (unsigned)(colbase + c);
                            // key: descending value, ascending index on ties
                            unsigned long long key =
                                ((unsigned long long)__float_as_uint(cvv[c]) << 32) |
                                (unsigned long long)(0xFFFFFFFFu - idx);
                            if (hot) {
                                int slot = nhot + __popc(mh & below);
                                if (slot < SEGCAP) seg[slot] = key;
                            } else {
                                int slot = ncold + __popc(mc & below);
                                if (slot < SEGCAP) seg[SEGCAP - 1 - slot] = key;
                            }
                        }
                        nhot += __popc(mh);
                        ncold += __popc(mc);
                    }
                }
            }
            // rotate state
            m33 = m32; m32 = m31; m31 = m30; m30 = m3n;
            hp2 = hp1; hp1 = hp0; hp0 = h;
            cv2 = cv1; cv1 = cv0; cv0 = vv;
        }
    }
    if (lane == 0) {
        unsigned nh = nhot > SEGCAP ? SEGCAP : (unsigned)nhot;
        unsigned ncl = ncold > SEGCAP ? SEGCAP : (unsigned)ncold;
        d_segcnt[segid] = nh | (ncl << 16);
    }
}

// One block per image. Gather hot keys only (~720) from segment fronts;
// fast-path bitonic sort if 200 <= nhot <= 1024, else radix over hot+cold.
__global__ void __launch_bounds__(1024) topk_kernel(float* __restrict__ out) {
    const int img = blockIdx.x;
    const int tid = threadIdx.x;
    const int lane = tid & 31;
    const int wrp = tid >> 5;

    __shared__ unsigned long long buf[1024];
    __shared__ int s_cnt;
    __shared__ unsigned scnt[SEGS_PER_IMG];
    __shared__ unsigned hist[256];
    __shared__ unsigned s_above, s_digit, s_total;

    const int cbase = img * SEGS_PER_IMG;
    for (int i = tid; i < SEGS_PER_IMG; i += 1024)
        scnt[i] = d_segcnt[cbase + i];
    if (tid == 0) s_cnt = 0;
    __syncthreads();

    // gather hot prefixes (warp per segment, ballot-aggregated shared counter)
    for (int s = wrp; s < SEGS_PER_IMG; s += 32) {
        int hot = (int)(scnt[s] & 0xffffu);
        const unsigned long long* seg = d_seg + (size_t)(cbase + s) * SEGCAP;
        for (int i0 = 0; i0 < hot; i0 += 32) {
            int i = i0 + lane;
            bool vld = i < hot;
            unsigned m = __ballot_sync(0xffffffffu, vld);
            int bs = 0;
            if (lane == 0) bs = atomicAdd(&s_cnt, __popc(m));
            bs = __shfl_sync(0xffffffffu, bs, 0);
            if (vld) {
                int pos = bs + __popc(m & ((1u << lane) - 1u));
                if (pos < 1024) buf[pos] = seg[i];
            }
        }
    }
    __syncthreads();
    int nhot = s_cnt;

    if (nhot >= TOPK && nhot <= 1024) {
        if (tid >= nhot) buf[tid] = 0ull;
    } else {
        // ---- fallback: radix-select over all hot+cold entries (off-distribution) ----
        const int NFLAT = SEGS_PER_IMG * SEGCAP;
        unsigned prefix = 0, above = 0;
        int shift = 24;
        bool done = false;
        for (int lev = 0; lev < 4 && !done; lev++) {
            shift = 24 - lev * 8;
            for (int i = tid; i < 256; i += 1024) hist[i] = 0;
            __syncthreads();
            for (int i = tid; i < NFLAT; i += 1024) {
                int s = i >> 9, slot = i & (SEGCAP - 1);
                int h = (int)(scnt[s] & 0xffffu), c = (int)(scnt[s] >> 16);
                if (slot < h || slot >= SEGCAP - c) {
                    unsigned vb = (unsigned)(d_seg[(size_t)(cbase + s) * SEGCAP + slot] >> 32);
                    if (lev == 0 || (vb >> (shift + 8)) == prefix)
                        atomicAdd(&hist[(vb >> shift) & 0xFFu], 1u);
                }
            }
            __syncthreads();
            if (tid == 0) {
                unsigned cum = 0; int dsel = 0;
                for (int b = 255; b >= 0; b--) {
                    if (above + cum + hist[b] >= TOPK || b == 0) { dsel = b; break; }
                    cum += hist[b];
                }
                s_above = above + cum;
                s_digit = (unsigned)dsel;
                s_total = above + cum + hist[dsel];
            }
            __syncthreads();
            above = s_above;
            prefix = (prefix << 8) | s_digit;
            done = (s_total <= 1024);
            __syncthreads();
        }
        if (tid == 0) s_cnt = 0;
        __syncthreads();
        for (int i = tid; i < NFLAT; i += 1024) {
            int s = i >> 9, slot = i & (SEGCAP - 1);
            int h = (int)(scnt[s] & 0xffffu), c = (int)(scnt[s] >> 16);
            if (slot < h || slot >= SEGCAP - c) {
                unsigned long long k = d_seg[(size_t)(cbase + s) * SEGCAP + slot];
                if (((unsigned)(k >> 32) >> shift) >= prefix) {
                    int pos = atomicAdd(&s_cnt, 1);
                    if (pos < 1024) buf[pos] = k;
                }
            }
        }
        __syncthreads();
        int m = s_cnt < 1024 ? s_cnt : 1024;
        if (tid >= m) buf[tid] = 0ull;
    }
    __syncthreads();

    // bitonic sort 1024 keys, descending
    for (int k = 2; k <= 1024; k <<= 1) {
        for (int j = k >> 1; j > 0; j >>= 1) {
            int ixj = tid ^ j;
            if (ixj > tid) {
                unsigned long long a = buf[tid], b = buf[ixj];
                bool sw = ((tid & k) == 0) ? (a < b) : (a > b);
                if (sw) { buf[tid] = b; buf[ixj] = a; }
            }
            __syncthreads();
        }
    }

    // emit: coords [B, K, 2] (row, col) then probs [B, K], all fp32
    float* coords = out;
    float* probs = out + (size_t)BATCH * TOPK * 2;
    if (tid < TOPK) {
        unsigned long long key = buf[tid];
        float prob; unsigned row, col;
        if (key == 0ull) {
            prob = 0.0f; row = 0; col = 0;
        } else {
            prob = __uint_as_float((unsigned)(key >> 32));
            unsigned idx = 0xFFFFFFFFu - (unsigned)(key & 0xFFFFFFFFull);
            row = idx / WW; col = idx % WW;
        }
        size_t o = (size_t)img * TOPK + tid;
        coords[o * 2 + 0] = (float)row;
        coords[o * 2 + 1] = (float)col;
        probs[o] = prob;
    }
}

extern "C" void kernel_launch(void* const* d_in, const int* in_sizes, int n_in,
                              void* d_out, int out_size) {
    const float* in = (const float*)d_in[0];
    float* out = (float*)d_out;

    dim3 grid(STRIPS / WPB, NBAND, BATCH);   // 2 x 32 x 32 = 2048 blocks
    nms_kernel<<<grid, 128>>>(in);
    topk_kernel<<<BATCH, 1024>>>(out);
}

// round 6
// speedup vs baseline: 5.7559x; 1.3275x over previous
#include <cuda_runtime.h>
#include <float.h>

#define BATCH 32
#define HH 1024
#define WW 1024
#define TOPK 200
#define HOT_T 0.9993f
#define STRIPS 8          // 8 strips x 128 cols
#define CPW 128           // columns per warp
#define WPB 4             // warps per block
#define RPB 64            // rows per band
#define NBAND (HH / RPB)  // 16
#define SEGS_PER_IMG (STRIPS * NBAND)   // 128
#define SEGCAP 1024       // >= worst-case distinct peaks per 128x64 tile (512)

// static device scratch — per-warp private segments (hot front, cold back)
__device__ unsigned long long d_seg[BATCH * SEGS_PER_IMG * SEGCAP];  // 32 MB
__device__ unsigned int d_segcnt[BATCH * SEGS_PER_IMG];              // hot | cold<<16

__device__ __forceinline__ float4 mk4(float x) { return make_float4(x, x, x, x); }

// Barrier-free, atomic-free, float4-vectorized 7x7 max-pool NMS.
// Warp owns a 128-col x 64-row tile; lane owns 4 columns; 4 rows per iter.
__global__ void __launch_bounds__(128) nms_kernel(const float* __restrict__ in) {
    const int img = blockIdx.z;
    const int wid = threadIdx.x >> 5;
    const int lane = threadIdx.x & 31;
    const int strip = blockIdx.x * WPB + wid;       // 0..7
    const int band = blockIdx.y;                    // 0..15
    const int out0 = strip * CPW;
    const int colbase = out0 + 4 * lane;
    const int ry0 = band * RPB;
    const int rend = ry0 + RPB + 2;
    const float* base = in + (size_t)img * HH * WW;

    const int segid = (img * NBAND + band) * STRIPS + strip;
    unsigned long long* seg = d_seg + (size_t)segid * SEGCAP;
    int nhot = 0, ncold = 0;

    const bool haloLane = (lane == 0) || (lane == 31);
    const int hcol = (lane == 0) ? (out0 - 4) : (out0 + CPW);
    const bool haloOK = haloLane && ((unsigned)hcol < WW);

    // rolling vertical state: h[r-1..r-3], m3 centered r-2..r-5, v[r-1..r-3]
    float4 hp0 = mk4(-FLT_MAX), hp1 = hp0, hp2 = hp0;
    float4 m30 = hp0, m31 = hp0, m32 = hp0, m33 = hp0;
    float4 cv0 = hp0, cv1 = hp0, cv2 = hp0;

    for (int rb = ry0 - 3; rb <= rend; rb += 4) {
        float4 v[4], q[4];
        #pragma unroll
        for (int k = 0; k < 4; k++) {
            int r = rb + k;
            bool rOK = ((unsigned)r < HH) && (r <= rend);
            v[k] = mk4(-FLT_MAX);
            q[k] = mk4(-FLT_MAX);
            if (rOK)
                v[k] = *reinterpret_cast<const float4*>(base + (size_t)r * WW + colbase);
            if (rOK && haloOK)
                q[k] = *reinterpret_cast<const float4*>(base + (size_t)r * WW + hcol);
        }
        #pragma unroll
        for (int k = 0; k < 4; k++) {
            int r = rb + k;
            float4 vv = v[k], qq = q[k];
            // own-quad prefix/suffix maxes
            float p1 = fmaxf(vv.x, vv.y);
            float p2 = fmaxf(p1, vv.z);
            float p3 = fmaxf(p2, vv.w);
            float s2 = fmaxf(vv.z, vv.w);
            float s1 = fmaxf(vv.y, s2);
            // halo-quad values (meaningful on lanes 0 / 31 only)
            float qs2 = fmaxf(qq.z, qq.w);
            float qs1 = fmaxf(qq.y, qs2);
            float qp1 = fmaxf(qq.x, qq.y);
            float qp2 = fmaxf(qp1, qq.z);

            float ls1 = __shfl_up_sync(0xffffffffu, s1, 1);
            float ls2 = __shfl_up_sync(0xffffffffu, s2, 1);
            float ls3 = __shfl_up_sync(0xffffffffu, vv.w, 1);
            float rp0 = __shfl_down_sync(0xffffffffu, vv.x, 1);
            float rp1 = __shfl_down_sync(0xffffffffu, p1, 1);
            float rp2 = __shfl_down_sync(0xffffffffu, p2, 1);
            if (lane == 0)  { ls1 = qs1;  ls2 = qs2;  ls3 = qq.w; }
            if (lane == 31) { rp0 = qq.x; rp1 = qp1;  rp2 = qp2;  }

            // horizontal 7-max
            float4 h;
            h.x = fmaxf(ls1, p3);
            h.y = fmaxf(fmaxf(ls2, rp0), p3);
            h.z = fmaxf(fmaxf(ls3, rp1), p3);
            h.w = fmaxf(rp2, p3);

            // vertical cascade
            float4 m3n, pooled;
            m3n.x = fmaxf(fmaxf(hp1.x, hp0.x), h.x);
            m3n.y = fmaxf(fmaxf(hp1.y, hp0.y), h.y);
            m3n.z = fmaxf(fmaxf(hp1.z, hp0.z), h.z);
            m3n.w = fmaxf(fmaxf(hp1.w, hp0.w), h.w);
            pooled.x = fmaxf(fmaxf(m33.x, hp2.x), m3n.x);
            pooled.y = fmaxf(fmaxf(m33.y, hp2.y), m3n.y);
            pooled.z = fmaxf(fmaxf(m33.z, hp2.z), m3n.z);
            pooled.w = fmaxf(fmaxf(m33.w, hp2.w), m3n.w);

            if (r >= ry0 + 3 && r <= rend) {
                bool pk0 = (cv2.x > 0.1f) && (pooled.x == cv2.x);
                bool pk1 = (cv2.y > 0.1f) && (pooled.y == cv2.y);
                bool pk2 = (cv2.z > 0.1f) && (pooled.z == cv2.z);
                bool pk3 = (cv2.w > 0.1f) && (pooled.w == cv2.w);
                int pcnt = (int)pk0 + (int)pk1 + (int)pk2 + (int)pk3;
                // first peak column in quad (>=2 peaks requires exact FP ties)
                int c = pk0 ? 0 : (pk1 ? 1 : (pk2 ? 2 : 3));
                float val = pk0 ? cv2.x : (pk1 ? cv2.y : (pk2 ? cv2.z : cv2.w));
                bool has = pcnt > 0;
                bool hot = has && (val > HOT_T);
                bool cold = has && !hot;
                unsigned mh = __ballot_sync(0xffffffffu, hot);
                unsigned mc = __ballot_sync(0xffffffffu, cold);
                unsigned mm = __ballot_sync(0xffffffffu, pcnt > 1);
                unsigned below = (1u << lane) - 1u;
                if (has) {
                    unsigned idx = (unsigned)(r - 3) * WW + (unsigned)(colbase + c);
                    unsigned long long key =
                        ((unsigned long long)__float_as_uint(val) << 32) |
                        (unsigned long long)(0xFFFFFFFFu - idx);
                    if (hot) {
                        int slot = nhot + __popc(mh & below);
                        if (slot < SEGCAP) seg[slot] = key;
                    } else {
                        int slot = ncold + __popc(mc & below);
                        if (slot < SEGCAP) seg[SEGCAP - 1 - slot] = key;
                    }
                }
                nhot += __popc(mh);
                ncold += __popc(mc);
                if (mm) {   // tie slow path: peaks after the first (near-never)
                    #pragma unroll
                    for (int cc = 1; cc < 4; cc++) {
                        bool p = (cc == 1 ? pk1 : cc == 2 ? pk2 : pk3) && (cc > c);
                        float v2 = (cc == 1 ? cv2.y : cc == 2 ? cv2.z : cv2.w);
                        bool h2 = p && (v2 > HOT_T);
                        bool c2 = p && !h2;
                        unsigned m2h = __ballot_sync(0xffffffffu, h2);
                        unsigned m2c = __ballot_sync(0xffffffffu, c2);
                        if (p) {
                            unsigned idx = (unsigned)(r - 3) * WW + (unsigned)(colbase + cc);
                            unsigned long long key =
                                ((unsigned long long)__float_as_uint(v2) << 32) |
                                (unsigned long long)(0xFFFFFFFFu - idx);
                            if (h2) {
                                int slot = nhot + __popc(m2h & below);
                                if (slot < SEGCAP) seg[slot] = key;
                            } else {
                                int slot = ncold + __popc(m2c & below);
                                if (slot < SEGCAP) seg[SEGCAP - 1 - slot] = key;
                            }
                        }
                        nhot += __popc(m2h);
                        ncold += __popc(m2c);
                    }
                }
            }
            m33 = m32; m32 = m31; m31 = m30; m30 = m3n;
            hp2 = hp1; hp1 = hp0; hp0 = h;
            cv2 = cv1; cv1 = cv0; cv0 = vv;
        }
    }
    if (lane == 0) {
        unsigned nh = nhot > SEGCAP ? SEGCAP : (unsigned)nhot;
        unsigned ncl = ncold > SEGCAP ? SEGCAP : (unsigned)ncold;
        d_segcnt[segid] = nh | (ncl << 16);
    }
}

// One block per image. Gather hot keys, hybrid register/shared bitonic sort.
__global__ void __launch_bounds__(1024) topk_kernel(float* __restrict__ out) {
    const int img = blockIdx.x;
    const int tid = threadIdx.x;
    const int lane = tid & 31;
    const int wrp = tid >> 5;

    __shared__ unsigned long long buf[1024];
    __shared__ int s_cnt;
    __shared__ unsigned scnt[SEGS_PER_IMG];
    __shared__ unsigned hist[256];
    __shared__ unsigned s_above, s_digit, s_total;

    const int cbase = img * SEGS_PER_IMG;
    for (int i = tid; i < SEGS_PER_IMG; i += 1024)
        scnt[i] = d_segcnt[cbase + i];
    if (tid == 0) s_cnt = 0;
    __syncthreads();

    // gather hot prefixes (warp per segment)
    for (int s = wrp; s < SEGS_PER_IMG; s += 32) {
        int hot = (int)(scnt[s] & 0xffffu);
        const unsigned long long* seg = d_seg + (size_t)(cbase + s) * SEGCAP;
        for (int i0 = 0; i0 < hot; i0 += 32) {
            int i = i0 + lane;
            bool vld = i < hot;
            unsigned m = __ballot_sync(0xffffffffu, vld);
            int bs = 0;
            if (lane == 0) bs = atomicAdd(&s_cnt, __popc(m));
            bs = __shfl_sync(0xffffffffu, bs, 0);
            if (vld) {
                int pos = bs + __popc(m & ((1u << lane) - 1u));
                if (pos < 1024) buf[pos] = seg[i];
            }
        }
    }
    __syncthreads();
    int nhot = s_cnt;

    if (nhot >= TOPK && nhot <= 1024) {
        if (tid >= nhot) buf[tid] = 0ull;
    } else {
        // ---- fallback: radix-select over all hot+cold entries ----
        const int NFLAT = SEGS_PER_IMG * SEGCAP;
        unsigned prefix = 0, above = 0;
        int shift = 24;
        bool done = false;
        for (int lev = 0; lev < 4 && !done; lev++) {
            shift = 24 - lev * 8;
            for (int i = tid; i < 256; i += 1024) hist[i] = 0;
            __syncthreads();
            for (int i = tid; i < NFLAT; i += 1024) {
                int s = i >> 10, slot = i & (SEGCAP - 1);
                int h = (int)(scnt[s] & 0xffffu), c = (int)(scnt[s] >> 16);
                if (slot < h || slot >= SEGCAP - c) {
                    unsigned vb = (unsigned)(d_seg[(size_t)(cbase + s) * SEGCAP + slot] >> 32);
                    if (lev == 0 || (vb >> (shift + 8)) == prefix)
                        atomicAdd(&hist[(vb >> shift) & 0xFFu], 1u);
                }
            }
            __syncthreads();
            if (tid == 0) {
                unsigned cum = 0; int dsel = 0;
                for (int b = 255; b >= 0; b--) {
                    if (above + cum + hist[b] >= TOPK || b == 0) { dsel = b; break; }
                    cum += hist[b];
                }
                s_above = above + cum;
                s_digit = (unsigned)dsel;
                s_total = above + cum + hist[dsel];
            }
            __syncthreads();
            above = s_above;
            prefix = (prefix << 8) | s_digit;
            done = (s_total <= 1024);
            __syncthreads();
        }
        if (tid == 0) s_cnt = 0;
        __syncthreads();
        for (int i = tid; i < NFLAT; i += 1024) {
            int s = i >> 10, slot = i & (SEGCAP - 1);
            int h = (int)(scnt[s] & 0xffffu), c = (int)(scnt[s] >> 16);
            if (slot < h || slot >= SEGCAP - c) {
                unsigned long long k = d_seg[(size_t)(cbase + s) * SEGCAP + slot];
                if (((unsigned)(k >> 32) >> shift) >= prefix) {
                    int pos = atomicAdd(&s_cnt, 1);
                    if (pos < 1024) buf[pos] = k;
                }
            }
        }
        __syncthreads();
        int m = s_cnt < 1024 ? s_cnt : 1024;
        if (tid >= m) buf[tid] = 0ull;
    }
    __syncthreads();

    // hybrid bitonic sort, descending: j>=32 via shared, j<32 via shfl_xor
    unsigned long long key = buf[tid];
    #pragma unroll
    for (int k = 2; k <= 1024; k <<= 1) {
        #pragma unroll
        for (int j = k >> 1; j >= 32; j >>= 1) {
            buf[tid] = key;
            __syncthreads();
            unsigned long long other = buf[tid ^ j];
            __syncthreads();
            bool takeMax = (((tid & k) == 0) == ((tid & j) == 0));
            key = (takeMax == (key > other)) ? key : other;
        }
        #pragma unroll
        for (int j = (k >> 1) < 16 ? (k >> 1) : 16; j >= 1; j >>= 1) {
            unsigned long long other = __shfl_xor_sync(0xffffffffu, key, j);
            bool takeMax = (((tid & k) == 0) == ((tid & j) == 0));
            key = (takeMax == (key > other)) ? key : other;
        }
    }

    // emit: coords [B, K, 2] (row, col) then probs [B, K], all fp32
    float* coords = out;
    float* probs = out + (size_t)BATCH * TOPK * 2;
    if (tid < TOPK) {
        float prob; unsigned row, col;
        if (key == 0ull) {
            prob = 0.0f; row = 0; col = 0;
        } else {
            prob = __uint_as_float((unsigned)(key >> 32));
            unsigned idx = 0xFFFFFFFFu - (unsigned)(key & 0xFFFFFFFFull);
            row = idx / WW; col = idx % WW;
        }
        size_t o = (size_t)img * TOPK + tid;
        coords[o * 2 + 0] = (float)row;
        coords[o * 2 + 1] = (float)col;
        probs[o] = prob;
    }
}

extern "C" void kernel_launch(void* const* d_in, const int* in_sizes, int n_in,
                              void* d_out, int out_size) {
    const float* in = (const float*)d_in[0];
    float* out = (float*)d_out;

    dim3 grid(STRIPS / WPB, NBAND, BATCH);   // 2 x 16 x 32 = 1024 blocks
    nms_kernel<<<grid, 128>>>(in);
    topk_kernel<<<BATCH, 1024>>>(out);
}